// round 15
// baseline (speedup 1.0000x reference)
#include <cuda_runtime.h>
#include <cuda_bf16.h>
#include <cuda_fp16.h>
#include <cstdint>

// Problem dims (fixed by the dataset)
#define N_   64
#define C_   64
#define T_   300
#define V_   25
#define S_   3
#define TT   4              // t positions per block
#define COLS 100            // TT*V_
#define TBLK 75             // T_/TT
#define NTHREADS 256

// xb row stride in 32-bit words (odd -> conflict-free word stores, step 9)
#define XBS  265

// -------- global folded parameters (written by prep kernel) --------
// W as GEMM2 A-operand frags (row-major o x k): [s][ot][kt][lane] uint4
__device__ __align__(16) uint4 g_Wa[S_ * 4 * 4 * 32];
__device__ __align__(16) uint4 g_Af[S_ * 2 * 2 * 2 * 32]; // Ae^T fp16 frags [s][mt][kt][hl][lane]
__device__ __align__(16) float g_ab[128];                // alpha | bshift

// ---------------- fp16 / mma helpers ----------------
// packhf(hi_elem, lo_elem): low 16 bits = f16(lo_elem)
__device__ __forceinline__ uint32_t packhf(float hi, float lo) {
    uint32_t d;
    asm("cvt.rn.f16x2.f32 %0, %1, %2;" : "=r"(d) : "f"(hi), "f"(lo));
    return d;
}
__device__ __forceinline__ void mma16816f(float* c, const uint32_t* a,
                                          uint32_t b0, uint32_t b1) {
    asm volatile(
        "mma.sync.aligned.m16n8k16.row.col.f32.f16.f16.f32 "
        "{%0,%1,%2,%3}, {%4,%5,%6,%7}, {%8,%9}, {%0,%1,%2,%3};"
        : "+f"(c[0]), "+f"(c[1]), "+f"(c[2]), "+f"(c[3])
        : "r"(a[0]), "r"(a[1]), "r"(a[2]), "r"(a[3]), "r"(b0), "r"(b1));
}
__device__ __forceinline__ void ldsm_x4(uint32_t* r, uint32_t addr) {
    asm volatile(
        "ldmatrix.sync.aligned.m8n8.x4.shared.b16 {%0,%1,%2,%3}, [%4];"
        : "=r"(r[0]), "=r"(r[1]), "=r"(r[2]), "=r"(r[3]) : "r"(addr));
}
__device__ __forceinline__ uint32_t smem_u32_of(const void* p) {
    uint32_t a;
    asm("{ .reg .u64 t; cvta.to.shared.u64 t, %1; cvt.u32.u64 %0, t; }"
        : "=r"(a) : "l"(p));
    return a;
}

// ---------------- prep: fold params (tiny, few blocks) ----------------
__global__ void unit_gcn_prep(const float* __restrict__ pA,
                              const float* __restrict__ pPA1,
                              const float* __restrict__ pPA2,
                              const float* __restrict__ pWc,
                              const float* __restrict__ pbc,
                              const float* __restrict__ pgamma,
                              const float* __restrict__ pbeta,
                              const float* __restrict__ prmean,
                              const float* __restrict__ prvar) {
    int tid = blockIdx.x * blockDim.x + threadIdx.x;

    // W fp16 A-operand fragments (row-major o x k). Hi only.
    // a0=W[o][k0,k0+1], a1=W[o+8][..], a2=W[o][k0+8,k0+9], a3=W[o+8][..].
    for (int i = tid; i < S_ * 4 * 4 * 32; i += blockDim.x * gridDim.x) {
        int lane = i & 31;
        int kt = (i >> 5) & 3;
        int ot = (i >> 7) & 3;
        int s  = i >> 9;
        int o  = ot * 16 + (lane >> 2);
        int k0 = kt * 16 + (lane & 3) * 2;
        const float* w0 = pWc + (s * 64 + o) * 64;
        const float* w8 = w0 + 8 * 64;
        uint4 frag;
        frag.x = packhf(w0[k0 + 1], w0[k0]);
        frag.y = packhf(w8[k0 + 1], w8[k0]);
        frag.z = packhf(w0[k0 + 9], w0[k0 + 8]);
        frag.w = packhf(w8[k0 + 9], w8[k0 + 8]);
        g_Wa[i] = frag;
    }

    // Ae^T fp16 fragments for GEMM1 A operand (row-major 32x32), hi + residual.
    for (int i = tid; i < S_ * 2 * 2 * 2 * 32; i += blockDim.x * gridDim.x) {
        int lane = i & 31;
        int hl = (i >> 5) & 1;
        int kt = (i >> 6) & 1;
        int mt = (i >> 7) & 1;
        int s  = i >> 8;
        int gm = mt * 16 + (lane >> 2);
        int k0 = kt * 16 + (lane & 3) * 2;
        float e[8];
        int ms[2] = {gm, gm + 8};
        int ks[4] = {k0, k0 + 1, k0 + 8, k0 + 9};
#pragma unroll
        for (int kk = 0; kk < 4; kk++)
#pragma unroll
            for (int mm = 0; mm < 2; mm++) {
                int m = ms[mm], k = ks[kk];
                float v = 0.0f;
                if (m < V_ && k < V_) {
                    int idx = (s * V_ + k) * V_ + m;
                    v = pA[idx] * pPA1[idx] + pPA2[idx];
                }
                e[kk * 2 + mm] = v;
            }
        if (hl) {
#pragma unroll
            for (int q = 0; q < 8; q++) {
                float h = __half2float(__float2half_rn(e[q]));
                e[q] = e[q] - h;
            }
        }
        uint4 frag;
        frag.x = packhf(e[2], e[0]);
        frag.y = packhf(e[3], e[1]);
        frag.z = packhf(e[6], e[4]);
        frag.w = packhf(e[7], e[5]);
        g_Af[i] = frag;
    }

    // BN fold: out = gemm*alpha + bshift (+x, relu). Bias folded into bshift.
    if (tid < C_) {
        float sc = pgamma[tid] / sqrtf(prvar[tid] + 1e-5f);
        float btot = pbc[tid] + pbc[64 + tid] + pbc[128 + tid];
        g_ab[tid] = sc;
        g_ab[64 + tid] = btot * sc + (pbeta[tid] - prmean[tid] * sc);
    }
}

// ---------------- main fused kernel ----------------
// smem layout (float index). A2 (hi only) double-buffered: [col][kw], 36-word rows.
#define AB_O    0                     // 128: alpha|bshift
#define A2H0_O  128                   // 112 x 36 = 4032
#define A2H1_O  4224                  // 4032 (64-word pad between buffers)
#define XBH_O   8320                  // 16 x 265 = 4240 (fp16 x, k-pair packed)
#define SMEM_FLOATS 12560
#define SMEM_BYTES  (SMEM_FLOATS * 4) // 50240

struct G1Ctx {
    uint32_t* xbh;
    int wid, lane;
};

// GEMM1 for subset s, writing A2 hi buffer. fp16, 2 chains (Ae hi+lo).
__device__ __forceinline__ void gemm1_subset(const G1Ctx& g, int s,
                                             uint32_t* a2h) {
    const int wid = g.wid, lane = g.lane;
    uint4 AH[2][2], AL[2][2];
#pragma unroll
    for (int mt = 0; mt < 2; mt++)
#pragma unroll
        for (int kt = 0; kt < 2; kt++) {
            AH[mt][kt] = __ldg(g_Af + ((((s * 2 + mt) * 2 + kt) * 2 + 0) * 32) + lane);
            AL[mt][kt] = __ldg(g_Af + ((((s * 2 + mt) * 2 + kt) * 2 + 1) * 32) + lane);
        }

#pragma unroll
    for (int nt = 0; nt < 4; nt++) {
        float d1[2][4];
#pragma unroll
        for (int i = 0; i < 2; i++)
#pragma unroll
            for (int q = 0; q < 4; q++) d1[i][q] = 0.0f;

        const int nn = wid * 32 + nt * 8 + (lane >> 2);
#pragma unroll
        for (int kt = 0; kt < 2; kt++) {
            const int rb = kt * 8 + (lane & 3);
            uint32_t bh0 = g.xbh[rb * XBS + nn];
            uint32_t bh1 = g.xbh[(rb + 4) * XBS + nn];
#pragma unroll
            for (int mt = 0; mt < 2; mt++) {
                mma16816f(d1[mt], (const uint32_t*)&AH[mt][kt], bh0, bh1);
                mma16816f(d1[mt], (const uint32_t*)&AL[mt][kt], bh0, bh1);
            }
        }

        // pack this nt slice into A2 [col][kw] as fp16 hi
        const int n0 = wid * 32 + nt * 8 + (lane & 3) * 2;
        const int cw = (n0 & 63) >> 1;
        const int tt = n0 >> 6;
#pragma unroll
        for (int mt = 0; mt < 2; mt++) {
            const int gm = mt * 16 + (lane >> 2);
            const float* dd = d1[mt];
            if (gm < V_) {
                int m2 = tt * 25 + gm;
                a2h[m2 * 36 + cw] = packhf(dd[1], dd[0]);
            }
            if (gm + 8 < V_) {
                int m2 = tt * 25 + gm + 8;
                a2h[m2 * 36 + cw] = packhf(dd[3], dd[2]);
            }
        }
    }
}

// GEMM2' for subset s: D[o][col] += W[o,k] . xa[k,col].
// W = A-operand (gmem frags), xa = B-operand via ldmatrix from A2.
// Warp (ot, wx): ot -> 16 o-rows, wx -> col-tiles [wx*7 .. ) (7 or 6 tiles).
__device__ __forceinline__ void gemm2_subset(float acc[7][4], int s,
                                             uint32_t abase_s,
                                             int ot, int wx, int lane) {
    const uint4* was = g_Wa + ((s * 4 + ot) * 4) * 32 + lane;
    const int npair = wx ? 3 : 4;
    const uint32_t rowsel =
        (uint32_t)(((lane & 7) + ((lane >> 4) << 3)) * 144 + ((lane >> 3) & 1) * 16);
    const uint32_t wxoff = (uint32_t)(wx ? 56 * 144 : 0);
#pragma unroll
    for (int kt = 0; kt < 4; kt++) {
        uint4 Wf = __ldg(was + kt * 32);
#pragma unroll
        for (int p = 0; p < 4; p++) {
            if (p < npair) {
                uint32_t addr = abase_s + wxoff + (uint32_t)(p * 16 * 144 + kt * 32)
                                + rowsel;
                uint32_t b[4];
                ldsm_x4(b, addr);
                mma16816f(acc[2 * p], (const uint32_t*)&Wf, b[0], b[1]);
                if (!(wx == 0 && p == 3))
                    mma16816f(acc[2 * p + 1], (const uint32_t*)&Wf, b[2], b[3]);
            }
        }
    }
}

__global__ void __launch_bounds__(NTHREADS, 2)
unit_gcn_main(const float* __restrict__ x, float* __restrict__ out) {
    const int n  = blockIdx.y;
    const int bx = blockIdx.x;       // t-tile
    const int t0 = bx * TT;
    const int tid = threadIdx.x;
    const int wid = tid >> 5;
    const int lane = tid & 31;

    extern __shared__ float sm[];
    float* ab = sm + AB_O;
    uint32_t* xbh = (uint32_t*)(sm + XBH_O);

    // Stage BN constants
    if (tid < 128) ab[tid] = g_ab[tid];

    // Zero A2 tail rows 100..111 (both buffers) — read by ldsm of the padded
    // col-tiles; garbage fp16 there would inject NaN into masked-but-summed acc.
    for (int i = tid; i < 12 * 36; i += NTHREADS) {
        ((uint32_t*)(sm + A2H0_O))[100 * 36 + i] = 0u;
        ((uint32_t*)(sm + A2H1_O))[100 * 36 + i] = 0u;
    }
    // Zero xb pad rows 13..15 (k = 26..31). Row 12 (k=24,25): wp=12 packs 0 hi.
    for (int i = tid; i < 3 * XBS; i += NTHREADS) {
        xbh[13 * XBS + i] = 0u;
    }
    // staging below writes disjoint regions — no barrier needed before it.

    // Stage x tile as k-pair-packed fp16 words for GEMM1 B (hi only).
    {
#pragma unroll
        for (int r = 0; r < 13; r++) {
            int q  = tid + NTHREADS * r;
            int c  = q / 52;
            int rm = q - c * 52;
            int tt = rm / 13;
            int wp = rm - tt * 13;
            const float* xr = x + (n * 64 + c) * 7500 + bx * 100 + tt * 25 + wp * 2;
            float v0 = __ldg(xr);
            float v1 = (wp < 12) ? __ldg(xr + 1) : 0.0f;
            xbh[wp * XBS + tt * 64 + c] = packhf(v1, v0);
        }
    }
    __syncthreads();

    const int ot = wid & 3;          // o-tile (16 channels)
    const int wx = wid >> 2;         // col-tile half

    float acc[7][4];
#pragma unroll
    for (int j = 0; j < 7; j++)
#pragma unroll
        for (int q = 0; q < 4; q++) acc[j][q] = 0.0f;

    const uint32_t a2h0_u = smem_u32_of(sm + A2H0_O);
    const uint32_t a2buf = (uint32_t)((A2H1_O - A2H0_O) * 4);

    G1Ctx g;
    g.xbh = xbh; g.wid = wid; g.lane = lane;
    uint32_t* a2h_b[2] = {(uint32_t*)(sm + A2H0_O), (uint32_t*)(sm + A2H1_O)};

    // ---- software pipeline over subsets ----
    gemm1_subset(g, 0, a2h_b[0]);
    __syncthreads();                                   // A2(0) ready
#pragma unroll
    for (int s = 0; s < S_; s++) {
        if (s < S_ - 1)
            gemm1_subset(g, s + 1, a2h_b[(s + 1) & 1]);
        gemm2_subset(acc, s,
                     a2h0_u + ((s & 1) ? a2buf : 0u),
                     ot, wx, lane);
        if (s < S_ - 1) __syncthreads();               // A2(s+1) ready; G2(s) reads done
    }

    // -------- Epilogue: BN + residual + relu, vectorized float2 ------------
    {
        const int o_lo = ot * 16 + (lane >> 2);
        const float al0 = ab[o_lo],      al1 = ab[o_lo + 8];
        const float bs0 = ab[64 + o_lo], bs1 = ab[64 + o_lo + 8];
        const int cbase = n * 480000 + t0 * 25;
        const int ntile = wx ? 6 : 7;
#pragma unroll
        for (int j = 0; j < 7; j++) {
            if (j < ntile) {
                int gt = wx * 7 + j;
                int col0 = gt * 8 + (lane & 3) * 2;
                if (col0 < COLS) {
                    int idx0 = cbase + o_lo * 7500 + col0;
                    int idx1 = idx0 + 8 * 7500;
                    float2 r0 = *(const float2*)(x + idx0);
                    float2 r1 = *(const float2*)(x + idx1);
                    float2 y0, y1;
                    y0.x = fmaxf(fmaf(acc[j][0], al0, bs0) + r0.x, 0.0f);
                    y0.y = fmaxf(fmaf(acc[j][1], al0, bs0) + r0.y, 0.0f);
                    y1.x = fmaxf(fmaf(acc[j][2], al1, bs1) + r1.x, 0.0f);
                    y1.y = fmaxf(fmaf(acc[j][3], al1, bs1) + r1.y, 0.0f);
                    *(float2*)(out + idx0) = y0;
                    *(float2*)(out + idx1) = y1;
                }
            }
        }
    }
}

extern "C" void kernel_launch(void* const* d_in, const int* in_sizes, int n_in,
                              void* d_out, int out_size) {
    const float* x     = (const float*)d_in[0];
    const float* A     = (const float*)d_in[1];
    const float* PA1   = (const float*)d_in[2];
    const float* PA2   = (const float*)d_in[3];
    const float* Wc    = (const float*)d_in[4];
    const float* bc    = (const float*)d_in[5];
    const float* gamma = (const float*)d_in[6];
    const float* beta  = (const float*)d_in[7];
    const float* rmean = (const float*)d_in[8];
    const float* rvar  = (const float*)d_in[9];
    float* out = (float*)d_out;

    unit_gcn_prep<<<8, 256>>>(A, PA1, PA2, Wc, bc, gamma, beta, rmean, rvar);

    cudaFuncSetAttribute(unit_gcn_main,
                         cudaFuncAttributeMaxDynamicSharedMemorySize, SMEM_BYTES);
    dim3 grid(TBLK, N_);
    unit_gcn_main<<<grid, NTHREADS, SMEM_BYTES>>>(x, out);
}

// round 16
// speedup vs baseline: 1.0695x; 1.0695x over previous
#include <cuda_runtime.h>
#include <cuda_bf16.h>
#include <cuda_fp16.h>
#include <cstdint>

// Problem dims (fixed by the dataset)
#define N_   64
#define C_   64
#define T_   300
#define V_   25
#define S_   3
#define TT   4              // t positions per block
#define COLS 100            // TT*V_
#define TBLK 75             // T_/TT
#define NTHREADS 256

// xb row stride in 32-bit words (odd -> conflict-free word stores, step 9)
#define XBS  265

// -------- global folded parameters (written by prep kernel) --------
__device__ __align__(16) uint2 g_Wh[S_ * 4 * 8 * 32];   // W fp16 frags [s][kt][ntg][lane]
__device__ __align__(16) uint4 g_Af[S_ * 2 * 2 * 32];   // Ae^T fp16 frags [s][mt][kt][lane] (hi only)
__device__ __align__(16) float g_ab[128];                // alpha | bshift

// ---------------- fp16 / mma helpers ----------------
// packhf(hi_elem, lo_elem): low 16 bits = f16(lo_elem)
__device__ __forceinline__ uint32_t packhf(float hi, float lo) {
    uint32_t d;
    asm("cvt.rn.f16x2.f32 %0, %1, %2;" : "=r"(d) : "f"(hi), "f"(lo));
    return d;
}
__device__ __forceinline__ void mma16816f(float* c, const uint32_t* a,
                                          uint32_t b0, uint32_t b1) {
    asm volatile(
        "mma.sync.aligned.m16n8k16.row.col.f32.f16.f16.f32 "
        "{%0,%1,%2,%3}, {%4,%5,%6,%7}, {%8,%9}, {%0,%1,%2,%3};"
        : "+f"(c[0]), "+f"(c[1]), "+f"(c[2]), "+f"(c[3])
        : "r"(a[0]), "r"(a[1]), "r"(a[2]), "r"(a[3]), "r"(b0), "r"(b1));
}
__device__ __forceinline__ void ldsm_x4(uint32_t* r, uint32_t addr) {
    asm volatile(
        "ldmatrix.sync.aligned.m8n8.x4.shared.b16 {%0,%1,%2,%3}, [%4];"
        : "=r"(r[0]), "=r"(r[1]), "=r"(r[2]), "=r"(r[3]) : "r"(addr));
}
__device__ __forceinline__ uint32_t smem_u32_of(const void* p) {
    uint32_t a;
    asm("{ .reg .u64 t; cvta.to.shared.u64 t, %1; cvt.u32.u64 %0, t; }"
        : "=r"(a) : "l"(p));
    return a;
}

// ---------------- prep: fold params (tiny, few blocks) ----------------
__global__ void unit_gcn_prep(const float* __restrict__ pA,
                              const float* __restrict__ pPA1,
                              const float* __restrict__ pPA2,
                              const float* __restrict__ pWc,
                              const float* __restrict__ pbc,
                              const float* __restrict__ pgamma,
                              const float* __restrict__ pbeta,
                              const float* __restrict__ prmean,
                              const float* __restrict__ prvar) {
    int tid = blockIdx.x * blockDim.x + threadIdx.x;

    // W fp16 fragments for GEMM2 B operand (col-major KxN). Hi only.
    for (int i = tid; i < S_ * 4 * 8 * 32; i += blockDim.x * gridDim.x) {
        int lane = i & 31;
        int ntg  = (i >> 5) & 7;
        int kt   = (i >> 8) & 3;
        int s    = i >> 10;
        int n  = ntg * 8 + (lane >> 2);
        int k0 = kt * 16 + (lane & 3) * 2;
        const float* wr = pWc + (s * 64 + n) * 64;
        uint2 frag;
        frag.x = packhf(wr[k0 + 1], wr[k0]);
        frag.y = packhf(wr[k0 + 9], wr[k0 + 8]);
        g_Wh[i] = frag;
    }

    // Ae^T fp16 fragments for GEMM1 A operand (row-major 32x32). Hi only.
    for (int i = tid; i < S_ * 2 * 2 * 32; i += blockDim.x * gridDim.x) {
        int lane = i & 31;
        int kt = (i >> 5) & 1;
        int mt = (i >> 6) & 1;
        int s  = i >> 7;
        int gm = mt * 16 + (lane >> 2);
        int k0 = kt * 16 + (lane & 3) * 2;
        float e[8];
        int ms[2] = {gm, gm + 8};
        int ks[4] = {k0, k0 + 1, k0 + 8, k0 + 9};
#pragma unroll
        for (int kk = 0; kk < 4; kk++)
#pragma unroll
            for (int mm = 0; mm < 2; mm++) {
                int m = ms[mm], k = ks[kk];
                float v = 0.0f;
                if (m < V_ && k < V_) {
                    int idx = (s * V_ + k) * V_ + m;
                    v = pA[idx] * pPA1[idx] + pPA2[idx];
                }
                e[kk * 2 + mm] = v;
            }
        uint4 frag;
        frag.x = packhf(e[2], e[0]);
        frag.y = packhf(e[3], e[1]);
        frag.z = packhf(e[6], e[4]);
        frag.w = packhf(e[7], e[5]);
        g_Af[i] = frag;
    }

    // BN fold: out = gemm*alpha + bshift (+x, relu). Bias folded into bshift.
    if (tid < C_) {
        float sc = pgamma[tid] / sqrtf(prvar[tid] + 1e-5f);
        float btot = pbc[tid] + pbc[64 + tid] + pbc[128 + tid];
        g_ab[tid] = sc;
        g_ab[64 + tid] = btot * sc + (pbeta[tid] - prmean[tid] * sc);
    }
}

// ---------------- main fused kernel ----------------
// smem layout (float index). A2 (hi only) double-buffered: [m][kw], 36-word rows.
#define AB_O    0                     // 128: alpha|bshift
#define A2H0_O  128                   // 4032
#define A2H1_O  4224                  // 4032 (64-word pad between buffers)
#define XBH_O   8320                  // 16 x 265 = 4240 (fp16 x, k-pair packed)
#define SMEM_FLOATS 12560
#define SMEM_BYTES  (SMEM_FLOATS * 4) // 50240

struct G1Ctx {
    uint32_t* xbh;
    int wid, lane;
};

// GEMM1 for subset s, writing A2 hi buffer. fp16, 1 chain (Ae hi only).
__device__ __forceinline__ void gemm1_subset(const G1Ctx& g, int s,
                                             uint32_t* a2h) {
    const int wid = g.wid, lane = g.lane;
    uint4 AH[2][2];
#pragma unroll
    for (int mt = 0; mt < 2; mt++)
#pragma unroll
        for (int kt = 0; kt < 2; kt++)
            AH[mt][kt] = __ldg(g_Af + (((s * 2 + mt) * 2 + kt) * 32) + lane);

#pragma unroll
    for (int nt = 0; nt < 4; nt++) {
        float d1[2][4];
#pragma unroll
        for (int i = 0; i < 2; i++)
#pragma unroll
            for (int q = 0; q < 4; q++) d1[i][q] = 0.0f;

        const int nn = wid * 32 + nt * 8 + (lane >> 2);
#pragma unroll
        for (int kt = 0; kt < 2; kt++) {
            const int rb = kt * 8 + (lane & 3);
            uint32_t bh0 = g.xbh[rb * XBS + nn];
            uint32_t bh1 = g.xbh[(rb + 4) * XBS + nn];
#pragma unroll
            for (int mt = 0; mt < 2; mt++)
                mma16816f(d1[mt], (const uint32_t*)&AH[mt][kt], bh0, bh1);
        }

        // pack this nt slice into A2 [m][kw] as fp16 hi
        const int n0 = wid * 32 + nt * 8 + (lane & 3) * 2;
        const int cw = (n0 & 63) >> 1;
        const int tt = n0 >> 6;
#pragma unroll
        for (int mt = 0; mt < 2; mt++) {
            const int gm = mt * 16 + (lane >> 2);
            const float* dd = d1[mt];
            if (gm < V_) {
                int m2 = tt * 25 + gm;
                a2h[m2 * 36 + cw] = packhf(dd[1], dd[0]);
            }
            if (gm + 8 < V_) {
                int m2 = tt * 25 + gm + 8;
                a2h[m2 * 36 + cw] = packhf(dd[3], dd[2]);
            }
        }
    }
}

// GEMM2 for subset s reading A2 hi buffer at byte base abase_s.
__device__ __forceinline__ void gemm2_subset(float acc[2][4][4], int s,
                                             uint32_t abase_s,
                                             int wy, int wx, int lane) {
    const uint2* wfs = g_Wh + (s * 4) * 8 * 32 + lane;
#pragma unroll
    for (int kt = 0; kt < 4; kt++) {
        uint2 Bf[4];
#pragma unroll
        for (int j = 0; j < 4; j++)
            Bf[j] = __ldg(wfs + (kt * 8 + wx * 4 + j) * 32);

#pragma unroll
        for (int mti = 0; mti < 2; mti++) {
            if (!(wy == 3 && mti == 1)) {   // rows 112..127 dead
                const uint32_t abase =
                    abase_s + (uint32_t)((wy * 2 + mti) * 16 * 144 + kt * 32);
                uint32_t ah[4];
                ldsm_x4(ah, abase);
#pragma unroll
                for (int j = 0; j < 4; j++)
                    mma16816f(acc[mti][j], ah, Bf[j].x, Bf[j].y);
            }
        }
    }
}

__global__ void __launch_bounds__(NTHREADS, 2)
unit_gcn_main(const float* __restrict__ x, float* __restrict__ out) {
    const int n  = blockIdx.y;
    const int bx = blockIdx.x;       // t-tile
    const int t0 = bx * TT;
    const int tid = threadIdx.x;
    const int wid = tid >> 5;
    const int lane = tid & 31;

    extern __shared__ float sm[];
    float* ab = sm + AB_O;
    uint32_t* xbh = (uint32_t*)(sm + XBH_O);

    // Stage BN constants
    if (tid < 128) ab[tid] = g_ab[tid];

    // Zero xb pad rows 13..15 (k = 26..31). Row 12 (k=24,25): wp=12 packs 0 hi.
    for (int i = tid; i < 3 * XBS; i += NTHREADS) {
        xbh[13 * XBS + i] = 0u;
    }
    // staging below writes rows 0..12 only (disjoint) — no barrier needed.

    // Stage x tile as k-pair-packed fp16 words for GEMM1 B (hi only).
    {
#pragma unroll
        for (int r = 0; r < 13; r++) {
            int q  = tid + NTHREADS * r;
            int c  = q / 52;
            int rm = q - c * 52;
            int tt = rm / 13;
            int wp = rm - tt * 13;
            const float* xr = x + (n * 64 + c) * 7500 + bx * 100 + tt * 25 + wp * 2;
            float v0 = __ldg(xr);
            float v1 = (wp < 12) ? __ldg(xr + 1) : 0.0f;
            xbh[wp * XBS + tt * 64 + c] = packhf(v1, v0);
        }
    }
    __syncthreads();

    const int wy = wid & 3;
    const int wx = wid >> 2;

    float acc[2][4][4];
#pragma unroll
    for (int i = 0; i < 2; i++)
#pragma unroll
        for (int j = 0; j < 4; j++)
#pragma unroll
            for (int q = 0; q < 4; q++) acc[i][j][q] = 0.0f;

    const uint32_t a2h0_u = smem_u32_of(sm + A2H0_O);
    const uint32_t a2buf = (uint32_t)((A2H1_O - A2H0_O) * 4);
    const uint32_t lds_lane_off = (uint32_t)((lane & 15) * 144 + (lane >> 4) * 16);

    G1Ctx g;
    g.xbh = xbh; g.wid = wid; g.lane = lane;
    uint32_t* a2h_b[2] = {(uint32_t*)(sm + A2H0_O), (uint32_t*)(sm + A2H1_O)};

    // ---- software pipeline over subsets ----
    gemm1_subset(g, 0, a2h_b[0]);
    __syncthreads();                                   // A2(0) ready
#pragma unroll
    for (int s = 0; s < S_; s++) {
        if (s < S_ - 1)
            gemm1_subset(g, s + 1, a2h_b[(s + 1) & 1]);
        gemm2_subset(acc, s,
                     a2h0_u + ((s & 1) ? a2buf : 0u) + lds_lane_off,
                     wy, wx, lane);
        if (s < S_ - 1) __syncthreads();               // A2(s+1) ready; G2(s) reads done
    }

    // -------- Epilogue: BN + residual(from gmem, L2-hot) + relu, store ------
    const int nb = wx * 32 + (lane & 3) * 2;
    float alv[8], bsv[8];
#pragma unroll
    for (int j = 0; j < 4; j++) {
        alv[2 * j]     = ab[nb + j * 8];
        alv[2 * j + 1] = ab[nb + j * 8 + 1];
        bsv[2 * j]     = ab[64 + nb + j * 8];
        bsv[2 * j + 1] = ab[64 + nb + j * 8 + 1];
    }

#pragma unroll
    for (int mti = 0; mti < 2; mti++) {
#pragma unroll
        for (int half = 0; half < 2; half++) {
            int m = (wy * 2 + mti) * 16 + (lane >> 2) + half * 8;
            if (m < COLS) {
                int tt = m / 25;
                int w  = m - tt * 25;
                int base = n * 480000 + (t0 + tt) * 25 + w;
#pragma unroll
                for (int j = 0; j < 4; j++) {
                    int o0 = nb + j * 8;
                    float c0 = acc[mti][j][half * 2];
                    float c1 = acc[mti][j][half * 2 + 1];
                    float r0 = __ldg(x + base + o0 * 7500);
                    float r1 = __ldg(x + base + (o0 + 1) * 7500);
                    float y0 = fmaf(c0, alv[2 * j], bsv[2 * j]) + r0;
                    float y1 = fmaf(c1, alv[2 * j + 1], bsv[2 * j + 1]) + r1;
                    out[base + o0 * 7500]       = fmaxf(y0, 0.0f);
                    out[base + (o0 + 1) * 7500] = fmaxf(y1, 0.0f);
                }
            }
        }
    }
}

extern "C" void kernel_launch(void* const* d_in, const int* in_sizes, int n_in,
                              void* d_out, int out_size) {
    const float* x     = (const float*)d_in[0];
    const float* A     = (const float*)d_in[1];
    const float* PA1   = (const float*)d_in[2];
    const float* PA2   = (const float*)d_in[3];
    const float* Wc    = (const float*)d_in[4];
    const float* bc    = (const float*)d_in[5];
    const float* gamma = (const float*)d_in[6];
    const float* beta  = (const float*)d_in[7];
    const float* rmean = (const float*)d_in[8];
    const float* rvar  = (const float*)d_in[9];
    float* out = (float*)d_out;

    unit_gcn_prep<<<8, 256>>>(A, PA1, PA2, Wc, bc, gamma, beta, rmean, rvar);

    cudaFuncSetAttribute(unit_gcn_main,
                         cudaFuncAttributeMaxDynamicSharedMemorySize, SMEM_BYTES);
    dim3 grid(TBLK, N_);
    unit_gcn_main<<<grid, NTHREADS, SMEM_BYTES>>>(x, out);
}

// round 17
// speedup vs baseline: 1.1445x; 1.0701x over previous
#include <cuda_runtime.h>
#include <cuda_bf16.h>
#include <cuda_fp16.h>
#include <cstdint>

// Problem dims (fixed by the dataset)
#define N_   64
#define C_   64
#define T_   300
#define V_   25
#define S_   3
#define TT   4              // t positions per block
#define COLS 100            // TT*V_
#define TBLK 75             // T_/TT
#define NTHREADS 256

// xb row stride in 32-bit words (odd -> conflict-free word stores, step 9)
#define XBS  265

// -------- global folded parameters (written by prep kernel) --------
__device__ __align__(16) uint2 g_Wh[S_ * 4 * 8 * 32];   // W fp16 frags [s][kt][ntg][lane]
__device__ __align__(16) uint4 g_Af[S_ * 2 * 2 * 32];   // Ae^T fp16 frags [s][mt][kt][lane] (hi only)
__device__ __align__(16) float g_ab[128];                // alpha | bshift

// ---------------- fp16 / mma helpers ----------------
// packhf(hi_elem, lo_elem): low 16 bits = f16(lo_elem)
__device__ __forceinline__ uint32_t packhf(float hi, float lo) {
    uint32_t d;
    asm("cvt.rn.f16x2.f32 %0, %1, %2;" : "=r"(d) : "f"(hi), "f"(lo));
    return d;
}
__device__ __forceinline__ void mma16816f(float* c, const uint32_t* a,
                                          uint32_t b0, uint32_t b1) {
    asm volatile(
        "mma.sync.aligned.m16n8k16.row.col.f32.f16.f16.f32 "
        "{%0,%1,%2,%3}, {%4,%5,%6,%7}, {%8,%9}, {%0,%1,%2,%3};"
        : "+f"(c[0]), "+f"(c[1]), "+f"(c[2]), "+f"(c[3])
        : "r"(a[0]), "r"(a[1]), "r"(a[2]), "r"(a[3]), "r"(b0), "r"(b1));
}
__device__ __forceinline__ void ldsm_x4(uint32_t* r, uint32_t addr) {
    asm volatile(
        "ldmatrix.sync.aligned.m8n8.x4.shared.b16 {%0,%1,%2,%3}, [%4];"
        : "=r"(r[0]), "=r"(r[1]), "=r"(r[2]), "=r"(r[3]) : "r"(addr));
}
__device__ __forceinline__ uint32_t smem_u32_of(const void* p) {
    uint32_t a;
    asm("{ .reg .u64 t; cvta.to.shared.u64 t, %1; cvt.u32.u64 %0, t; }"
        : "=r"(a) : "l"(p));
    return a;
}

// ---------------- prep: fold params (tiny, few blocks) ----------------
__global__ void unit_gcn_prep(const float* __restrict__ pA,
                              const float* __restrict__ pPA1,
                              const float* __restrict__ pPA2,
                              const float* __restrict__ pWc,
                              const float* __restrict__ pbc,
                              const float* __restrict__ pgamma,
                              const float* __restrict__ pbeta,
                              const float* __restrict__ prmean,
                              const float* __restrict__ prvar) {
    int tid = blockIdx.x * blockDim.x + threadIdx.x;

    // W fp16 fragments for GEMM2 B operand (col-major KxN). Hi only.
    for (int i = tid; i < S_ * 4 * 8 * 32; i += blockDim.x * gridDim.x) {
        int lane = i & 31;
        int ntg  = (i >> 5) & 7;
        int kt   = (i >> 8) & 3;
        int s    = i >> 10;
        int n  = ntg * 8 + (lane >> 2);
        int k0 = kt * 16 + (lane & 3) * 2;
        const float* wr = pWc + (s * 64 + n) * 64;
        uint2 frag;
        frag.x = packhf(wr[k0 + 1], wr[k0]);
        frag.y = packhf(wr[k0 + 9], wr[k0 + 8]);
        g_Wh[i] = frag;
    }

    // Ae^T fp16 fragments for GEMM1 A operand (row-major 32x32). Hi only.
    for (int i = tid; i < S_ * 2 * 2 * 32; i += blockDim.x * gridDim.x) {
        int lane = i & 31;
        int kt = (i >> 5) & 1;
        int mt = (i >> 6) & 1;
        int s  = i >> 7;
        int gm = mt * 16 + (lane >> 2);
        int k0 = kt * 16 + (lane & 3) * 2;
        float e[8];
        int ms[2] = {gm, gm + 8};
        int ks[4] = {k0, k0 + 1, k0 + 8, k0 + 9};
#pragma unroll
        for (int kk = 0; kk < 4; kk++)
#pragma unroll
            for (int mm = 0; mm < 2; mm++) {
                int m = ms[mm], k = ks[kk];
                float v = 0.0f;
                if (m < V_ && k < V_) {
                    int idx = (s * V_ + k) * V_ + m;
                    v = pA[idx] * pPA1[idx] + pPA2[idx];
                }
                e[kk * 2 + mm] = v;
            }
        uint4 frag;
        frag.x = packhf(e[2], e[0]);
        frag.y = packhf(e[3], e[1]);
        frag.z = packhf(e[6], e[4]);
        frag.w = packhf(e[7], e[5]);
        g_Af[i] = frag;
    }

    // BN fold: out = gemm*alpha + bshift (+x, relu). Bias folded into bshift.
    if (tid < C_) {
        float sc = pgamma[tid] / sqrtf(prvar[tid] + 1e-5f);
        float btot = pbc[tid] + pbc[64 + tid] + pbc[128 + tid];
        g_ab[tid] = sc;
        g_ab[64 + tid] = btot * sc + (pbeta[tid] - prmean[tid] * sc);
    }
}

// ---------------- main fused kernel ----------------
// smem layout (float index). A2 (hi only) double-buffered: [m][kw], 36-word rows.
#define AB_O    0                     // 128: alpha|bshift
#define A2H0_O  128                   // 4032
#define A2H1_O  4224                  // 4032 (64-word pad between buffers)
#define XBH_O   8320                  // 16 x 265 = 4240 (fp16 x, k-pair packed)
#define SMEM_FLOATS 12560
#define SMEM_BYTES  (SMEM_FLOATS * 4) // 50240 -> 3 CTAs/SM (150.7KB of 228KB)

struct G1Ctx {
    uint32_t* xbh;
    int wid, lane;
};

// GEMM1 for subset s, writing A2 hi buffer. fp16, 1 chain (Ae hi only).
__device__ __forceinline__ void gemm1_subset(const G1Ctx& g, int s,
                                             uint32_t* a2h) {
    const int wid = g.wid, lane = g.lane;
    uint4 AH[2][2];
#pragma unroll
    for (int mt = 0; mt < 2; mt++)
#pragma unroll
        for (int kt = 0; kt < 2; kt++)
            AH[mt][kt] = __ldg(g_Af + (((s * 2 + mt) * 2 + kt) * 32) + lane);

#pragma unroll
    for (int nt = 0; nt < 4; nt++) {
        float d1[2][4];
#pragma unroll
        for (int i = 0; i < 2; i++)
#pragma unroll
            for (int q = 0; q < 4; q++) d1[i][q] = 0.0f;

        const int nn = wid * 32 + nt * 8 + (lane >> 2);
#pragma unroll
        for (int kt = 0; kt < 2; kt++) {
            const int rb = kt * 8 + (lane & 3);
            uint32_t bh0 = g.xbh[rb * XBS + nn];
            uint32_t bh1 = g.xbh[(rb + 4) * XBS + nn];
#pragma unroll
            for (int mt = 0; mt < 2; mt++)
                mma16816f(d1[mt], (const uint32_t*)&AH[mt][kt], bh0, bh1);
        }

        // pack this nt slice into A2 [m][kw] as fp16 hi
        const int n0 = wid * 32 + nt * 8 + (lane & 3) * 2;
        const int cw = (n0 & 63) >> 1;
        const int tt = n0 >> 6;
#pragma unroll
        for (int mt = 0; mt < 2; mt++) {
            const int gm = mt * 16 + (lane >> 2);
            const float* dd = d1[mt];
            if (gm < V_) {
                int m2 = tt * 25 + gm;
                a2h[m2 * 36 + cw] = packhf(dd[1], dd[0]);
            }
            if (gm + 8 < V_) {
                int m2 = tt * 25 + gm + 8;
                a2h[m2 * 36 + cw] = packhf(dd[3], dd[2]);
            }
        }
    }
}

// GEMM2 for subset s reading A2 hi buffer at byte base abase_s.
__device__ __forceinline__ void gemm2_subset(float acc[2][4][4], int s,
                                             uint32_t abase_s,
                                             int wy, int wx, int lane) {
    const uint2* wfs = g_Wh + (s * 4) * 8 * 32 + lane;
#pragma unroll
    for (int kt = 0; kt < 4; kt++) {
        uint2 Bf[4];
#pragma unroll
        for (int j = 0; j < 4; j++)
            Bf[j] = __ldg(wfs + (kt * 8 + wx * 4 + j) * 32);

#pragma unroll
        for (int mti = 0; mti < 2; mti++) {
            if (!(wy == 3 && mti == 1)) {   // rows 112..127 dead
                const uint32_t abase =
                    abase_s + (uint32_t)((wy * 2 + mti) * 16 * 144 + kt * 32);
                uint32_t ah[4];
                ldsm_x4(ah, abase);
#pragma unroll
                for (int j = 0; j < 4; j++)
                    mma16816f(acc[mti][j], ah, Bf[j].x, Bf[j].y);
            }
        }
    }
}

__global__ void __launch_bounds__(NTHREADS, 3)
unit_gcn_main(const float* __restrict__ x, float* __restrict__ out) {
    const int n  = blockIdx.y;
    const int bx = blockIdx.x;       // t-tile
    const int t0 = bx * TT;
    const int tid = threadIdx.x;
    const int wid = tid >> 5;
    const int lane = tid & 31;

    extern __shared__ float sm[];
    float* ab = sm + AB_O;
    uint32_t* xbh = (uint32_t*)(sm + XBH_O);

    // Stage BN constants
    if (tid < 128) ab[tid] = g_ab[tid];

    // Zero xb pad rows 13..15 (k = 26..31). Row 12 (k=24,25): wp=12 packs 0 hi.
    for (int i = tid; i < 3 * XBS; i += NTHREADS) {
        xbh[13 * XBS + i] = 0u;
    }
    // staging below writes rows 0..12 only (disjoint) — no barrier needed.

    // Stage x tile as k-pair-packed fp16 words for GEMM1 B (hi only).
    {
#pragma unroll
        for (int r = 0; r < 13; r++) {
            int q  = tid + NTHREADS * r;
            int c  = q / 52;
            int rm = q - c * 52;
            int tt = rm / 13;
            int wp = rm - tt * 13;
            const float* xr = x + (n * 64 + c) * 7500 + bx * 100 + tt * 25 + wp * 2;
            float v0 = __ldg(xr);
            float v1 = (wp < 12) ? __ldg(xr + 1) : 0.0f;
            xbh[wp * XBS + tt * 64 + c] = packhf(v1, v0);
        }
    }
    __syncthreads();

    const int wy = wid & 3;
    const int wx = wid >> 2;

    float acc[2][4][4];
#pragma unroll
    for (int i = 0; i < 2; i++)
#pragma unroll
        for (int j = 0; j < 4; j++)
#pragma unroll
            for (int q = 0; q < 4; q++) acc[i][j][q] = 0.0f;

    const uint32_t a2h0_u = smem_u32_of(sm + A2H0_O);
    const uint32_t a2buf = (uint32_t)((A2H1_O - A2H0_O) * 4);
    const uint32_t lds_lane_off = (uint32_t)((lane & 15) * 144 + (lane >> 4) * 16);

    G1Ctx g;
    g.xbh = xbh; g.wid = wid; g.lane = lane;
    uint32_t* a2h_b[2] = {(uint32_t*)(sm + A2H0_O), (uint32_t*)(sm + A2H1_O)};

    // ---- software pipeline over subsets ----
    gemm1_subset(g, 0, a2h_b[0]);
    __syncthreads();                                   // A2(0) ready
#pragma unroll
    for (int s = 0; s < S_; s++) {
        if (s < S_ - 1)
            gemm1_subset(g, s + 1, a2h_b[(s + 1) & 1]);
        gemm2_subset(acc, s,
                     a2h0_u + ((s & 1) ? a2buf : 0u) + lds_lane_off,
                     wy, wx, lane);
        if (s < S_ - 1) __syncthreads();               // A2(s+1) ready; G2(s) reads done
    }

    // -------- Epilogue: BN + residual(from gmem, L2-hot) + relu, store ------
    // alpha/bshift read from smem at use (keeps peak regs <= 85 for occ=3).
    const int nb = wx * 32 + (lane & 3) * 2;
#pragma unroll
    for (int mti = 0; mti < 2; mti++) {
#pragma unroll
        for (int half = 0; half < 2; half++) {
            int m = (wy * 2 + mti) * 16 + (lane >> 2) + half * 8;
            if (m < COLS) {
                int tt = m / 25;
                int w  = m - tt * 25;
                int base = n * 480000 + (t0 + tt) * 25 + w;
#pragma unroll
                for (int j = 0; j < 4; j++) {
                    int o0 = nb + j * 8;
                    float c0 = acc[mti][j][half * 2];
                    float c1 = acc[mti][j][half * 2 + 1];
                    float r0 = __ldg(x + base + o0 * 7500);
                    float r1 = __ldg(x + base + (o0 + 1) * 7500);
                    float y0 = fmaf(c0, ab[o0], ab[64 + o0]) + r0;
                    float y1 = fmaf(c1, ab[o0 + 1], ab[64 + o0 + 1]) + r1;
                    out[base + o0 * 7500]       = fmaxf(y0, 0.0f);
                    out[base + (o0 + 1) * 7500] = fmaxf(y1, 0.0f);
                }
            }
        }
    }
}

extern "C" void kernel_launch(void* const* d_in, const int* in_sizes, int n_in,
                              void* d_out, int out_size) {
    const float* x     = (const float*)d_in[0];
    const float* A     = (const float*)d_in[1];
    const float* PA1   = (const float*)d_in[2];
    const float* PA2   = (const float*)d_in[3];
    const float* Wc    = (const float*)d_in[4];
    const float* bc    = (const float*)d_in[5];
    const float* gamma = (const float*)d_in[6];
    const float* beta  = (const float*)d_in[7];
    const float* rmean = (const float*)d_in[8];
    const float* rvar  = (const float*)d_in[9];
    float* out = (float*)d_out;

    unit_gcn_prep<<<8, 256>>>(A, PA1, PA2, Wc, bc, gamma, beta, rmean, rvar);

    cudaFuncSetAttribute(unit_gcn_main,
                         cudaFuncAttributeMaxDynamicSharedMemorySize, SMEM_BYTES);
    dim3 grid(TBLK, N_);
    unit_gcn_main<<<grid, NTHREADS, SMEM_BYTES>>>(x, out);
}